// round 16
// baseline (speedup 1.0000x reference)
#include <cuda_runtime.h>
#include <cstdint>

#define B_ 4
#define S_ 1024
#define E_ 1024
#define H_ 16
#define D_ 64

__device__ float g_qkv[3*B_*S_*E_];
__device__ float g_ctx[B_*S_*E_];
__device__ float g_xtf[B_*S_*E_];
__device__ float g_wtf[4*E_*E_];
__device__ float g_g[B_*E_];
__device__ float g_gq[B_*E_];
__device__ float g_gk[B_*E_];
__device__ float g_minv[B_];

__device__ __forceinline__ uint32_t fbits(float f) { return __float_as_uint(f); }

__device__ __forceinline__ uint32_t f2tf(float f) {
    uint32_t u;
    asm("cvt.rna.tf32.f32 %0, %1;" : "=r"(u) : "f"(f));
    return u;
}
__device__ __forceinline__ float tfround(float f) {
    return __uint_as_float(f2tf(f));
}

__device__ __forceinline__ void mma_tf32(float c[4],
    uint32_t a0, uint32_t a1, uint32_t a2, uint32_t a3,
    uint32_t b0, uint32_t b1)
{
    asm volatile(
        "mma.sync.aligned.m16n8k8.row.col.f32.tf32.tf32.f32 "
        "{%0,%1,%2,%3}, {%4,%5,%6,%7}, {%8,%9}, {%0,%1,%2,%3};"
        : "+f"(c[0]), "+f"(c[1]), "+f"(c[2]), "+f"(c[3])
        : "r"(a0), "r"(a1), "r"(a2), "r"(a3), "r"(b0), "r"(b1));
}

__device__ __forceinline__ void cp16(uint32_t saddr, const void* g) {
    asm volatile("cp.async.cg.shared.global [%0], [%1], 16;" :: "r"(saddr), "l"(g));
}

// ---------------------------------------------------------------------------
__global__ void __launch_bounds__(256) round_all(
    const float4* __restrict__ x,
    const float4* __restrict__ wq, const float4* __restrict__ wk,
    const float4* __restrict__ wv, const float4* __restrict__ wo)
{
    int idx = blockIdx.x * 256 + threadIdx.x;
    const float4* src;
    float4* dst;
    if (idx < (1 << 20)) {
        src = x + idx;
        dst = (float4*)g_xtf + idx;
    } else {
        int r = idx - (1 << 20);
        int w = r >> 18, o = r & ((1 << 18) - 1);
        const float4* s = (w == 0) ? wq : (w == 1) ? wk : (w == 2) ? wv : wo;
        src = s + o;
        dst = (float4*)g_wtf + ((size_t)w << 18) + o;
    }
    float4 v = *src;
    v.x = tfround(v.x); v.y = tfround(v.y);
    v.z = tfround(v.z); v.w = tfround(v.w);
    *dst = v;
}

// ---------------------------------------------------------------------------
__global__ void msum_kernel(const int* __restrict__ mask) {
    int b = threadIdx.x >> 5, lane = threadIdx.x & 31;
    float s = 0.f;
    for (int j = lane; j < S_; j += 32) s += (float)mask[b*S_ + j];
    #pragma unroll
    for (int o = 16; o; o >>= 1) s += __shfl_xor_sync(0xffffffffu, s, o);
    if (lane == 0) g_minv[b] = 1.0f / fmaxf(s, 1e-9f);
}

__global__ void mean_kernel(const float* __restrict__ x, const int* __restrict__ mask) {
    __shared__ float part[4][64];
    int b  = blockIdx.y;
    int e0 = blockIdx.x * 64;
    int el = threadIdx.x & 63, sq = threadIdx.x >> 6;
    float acc = 0.f;
    int sbeg = sq * 256;
    for (int s = sbeg; s < sbeg + 256; s++) {
        float m = (float)mask[b*S_ + s];
        acc += x[((size_t)s*B_ + b)*E_ + e0 + el] * m;
    }
    part[sq][el] = acc;
    __syncthreads();
    if (threadIdx.x < 64) {
        float t = part[0][el] + part[1][el] + part[2][el] + part[3][el];
        g_g[b*E_ + e0 + el] = t * g_minv[b];
    }
}

// ---------------------------------------------------------------------------
// tf32 GEMM core (R13/R15 proven); LDS.64 via k-permutation.
#define GPAD 24
#define GSTG (128*GPAD)

__device__ __forceinline__ void tgemm_body(
    const float* __restrict__ A, const float* __restrict__ W,
    const float* __restrict__ bias, float* __restrict__ Y,
    int permIn, int permOut, int roundOut, int bx, int by,
    float (*As)[GSTG], float (*Bs)[GSTG])
{
    const int tid = threadIdx.x;
    const int lane = tid & 31, warp = tid >> 5;
    const int wm = (warp & 1) * 64, wn = (warp >> 1) * 32;
    const int r4 = lane >> 2, c4 = lane & 3;

    uint32_t aBase = (uint32_t)__cvta_generic_to_shared(&As[0][0]);
    uint32_t bBase = (uint32_t)__cvta_generic_to_shared(&Bs[0][0]);

    int row0 = tid >> 2,         k40 = (tid & 3) * 4;
    int row1 = (tid + 256) >> 2, k41 = ((tid + 256) & 3) * 4;
    int am0 = by*128 + row0;
    int am1 = by*128 + row1;
    int ar0 = permIn ? ((am0 & 1023)*B_ + (am0 >> 10)) : am0;
    int ar1 = permIn ? ((am1 & 1023)*B_ + (am1 >> 10)) : am1;
    const float* ap0 = A + (size_t)ar0*1024 + k40;
    const float* ap1 = A + (size_t)ar1*1024 + k41;
    const float* wp0 = W + ((size_t)(bx*128 + row0))*1024 + k40;
    const float* wp1 = W + ((size_t)(bx*128 + row1))*1024 + k41;
    uint32_t ad0 = aBase + (row0*GPAD + k40)*4, ad1 = aBase + (row1*GPAD + k41)*4;
    uint32_t bd0 = bBase + (row0*GPAD + k40)*4, bd1 = bBase + (row1*GPAD + k41)*4;

    auto loadStage = [&](int stg, int k0) {
        uint32_t so = stg * GSTG * 4;
        cp16(ad0 + so, ap0 + k0);
        cp16(ad1 + so, ap1 + k0);
        cp16(bd0 + so, wp0 + k0);
        cp16(bd1 + so, wp1 + k0);
        asm volatile("cp.async.commit_group;" ::: "memory");
    };

    float acc[4][4][4];
    #pragma unroll
    for (int mi = 0; mi < 4; mi++)
        #pragma unroll
        for (int nj = 0; nj < 4; nj++)
            #pragma unroll
            for (int t = 0; t < 4; t++) acc[mi][nj][t] = 0.f;

    loadStage(0, 0);
    for (int ks = 0; ks < 64; ks++) {
        if (ks < 63) {
            loadStage((ks + 1) & 1, (ks + 1) * 16);
            asm volatile("cp.async.wait_group 1;" ::: "memory");
        } else {
            asm volatile("cp.async.wait_group 0;" ::: "memory");
        }
        __syncthreads();
        const float* as = As[ks & 1];
        const float* bs = Bs[ks & 1];
        #pragma unroll
        for (int kk = 0; kk < 16; kk += 8) {
            uint32_t af[4][4];
            #pragma unroll
            for (int mi = 0; mi < 4; mi++) {
                float2 lo = *(const float2*)(as + (wm + mi*16 + r4)*GPAD + kk + 2*c4);
                float2 hi = *(const float2*)(as + (wm + mi*16 + r4 + 8)*GPAD + kk + 2*c4);
                af[mi][0] = fbits(lo.x);
                af[mi][1] = fbits(hi.x);
                af[mi][2] = fbits(lo.y);
                af[mi][3] = fbits(hi.y);
            }
            #pragma unroll
            for (int nj = 0; nj < 4; nj++) {
                float2 bv = *(const float2*)(bs + (wn + nj*8 + r4)*GPAD + kk + 2*c4);
                uint32_t b0 = fbits(bv.x), b1 = fbits(bv.y);
                #pragma unroll
                for (int mi = 0; mi < 4; mi++)
                    mma_tf32(acc[mi][nj], af[mi][0], af[mi][1], af[mi][2], af[mi][3], b0, b1);
            }
        }
        __syncthreads();
    }

    #pragma unroll
    for (int mi = 0; mi < 4; mi++) {
        #pragma unroll
        for (int r2 = 0; r2 < 2; r2++) {
            int m = by*128 + wm + mi*16 + r4 + r2*8;
            int orow = permOut ? ((m & 1023)*B_ + (m >> 10)) : m;
            float* yp = Y + (size_t)orow*1024 + bx*128 + wn;
            const float* bi = bias + bx*128 + wn;
            #pragma unroll
            for (int nj = 0; nj < 4; nj++) {
                int c = nj*8 + 2*c4;
                float2 val;
                val.x = acc[mi][nj][r2*2 + 0] + bi[c];
                val.y = acc[mi][nj][r2*2 + 1] + bi[c + 1];
                if (roundOut) { val.x = tfround(val.x); val.y = tfround(val.y); }
                *(float2*)(yp + c) = val;
            }
        }
    }
}

__global__ void __launch_bounds__(256) tgemm_qkv(
    const float* __restrict__ bq, const float* __restrict__ bk,
    const float* __restrict__ bv, float* __restrict__ Y)
{
    __shared__ float As[2][GSTG];
    __shared__ float Bs[2][GSTG];
    int sel = blockIdx.z;
    const float* bi = (sel == 0) ? bq : (sel == 1) ? bk : bv;
    tgemm_body(g_xtf, g_wtf + (size_t)sel*E_*E_, bi, Y + (size_t)sel*B_*S_*E_,
               1, 0, sel == 2, blockIdx.x, blockIdx.y, As, Bs);
}

__global__ void __launch_bounds__(256) tgemm_wo(
    const float* __restrict__ bias, float* __restrict__ Y)
{
    __shared__ float As[2][GSTG];
    __shared__ float Bs[2][GSTG];
    tgemm_body(g_ctx, g_wtf + (size_t)3*E_*E_, bias, Y,
               0, 1, 0, blockIdx.x, blockIdx.y, As, Bs);
}

// ---------------------------------------------------------------------------
__global__ void gproj_kernel(const float* __restrict__ Wgq, const float* __restrict__ bgq,
                             const float* __restrict__ Wgk, const float* __restrict__ bgk)
{
    const float* Wg = blockIdx.y ? Wgk : Wgq;
    const float* bg = blockIdx.y ? bgk : bgq;
    float* out      = blockIdx.y ? g_gk : g_gq;
    int gw = (blockIdx.x * blockDim.x + threadIdx.x) >> 5;
    int lane = threadIdx.x & 31;
    int b = gw >> 10, o = gw & 1023;
    float acc = 0.f;
    #pragma unroll
    for (int e = lane * 4; e < E_; e += 128) {
        float4 gv = *(const float4*)&g_g[b*E_ + e];
        float4 wv = *(const float4*)&Wg[(size_t)o*E_ + e];
        acc += gv.x*wv.x + gv.y*wv.y + gv.z*wv.z + gv.w*wv.w;
    }
    #pragma unroll
    for (int of = 16; of; of >>= 1) acc += __shfl_xor_sync(0xffffffffu, acc, of);
    if (lane == 0) out[b*E_ + o] = acc + bg[o];
}

__global__ void gate_kernel(float* __restrict__ qkv,
                            const float* __restrict__ wvq, const float* __restrict__ bvq,
                            const float* __restrict__ wgq, const float* __restrict__ bgq,
                            const float* __restrict__ wvk, const float* __restrict__ bvk,
                            const float* __restrict__ wgk, const float* __restrict__ bgk)
{
    int z = blockIdx.y;
    float* buf        = qkv + (size_t)z * B_*S_*E_;
    const float* gbuf = z ? g_gk : g_gq;
    const float* wv   = z ? wvk : wvq;
    const float* bvp  = z ? bvk : bvq;
    const float* wg   = z ? wgk : wgq;
    const float* bgp  = z ? bgk : bgq;

    int gw   = (blockIdx.x * blockDim.x + threadIdx.x) >> 5;
    int lane = threadIdx.x & 31;
    int b = gw >> 14, h = (gw >> 10) & 15, s = gw & 1023;
    size_t off = ((size_t)(b*S_ + s))*E_ + h*D_;
    int goff = b*E_ + h*D_;
    float q0 = buf[off + lane],        q1 = buf[off + 32 + lane];
    float g0 = gbuf[goff + lane],      g1 = gbuf[goff + 32 + lane];
    float part = q0*wv[lane] + q1*wv[32 + lane] + g0*wg[lane] + g1*wg[32 + lane];
    #pragma unroll
    for (int o = 16; o; o >>= 1) part += __shfl_xor_sync(0xffffffffu, part, o);
    float alpha = 1.f / (1.f + __expf(-(part + bvp[0] + bgp[0])));
    buf[off + lane]      = tfround(q0 + alpha * (g0 - q0));
    buf[off + 32 + lane] = tfround(q1 + alpha * (g1 - q1));
}

// ---------------------------------------------------------------------------
// fused attention: 32 q-rows/CTA, 512 threads, 64-key chunks in a 4-deep
// cp.async ring (3 chunks in flight), ONE barrier per chunk iteration.
// Phase 2 float4-vectorized. All MMA operands pre-rounded tf32.
#define SCP 1028
#define KVW2 72
#define CHN 64
#define ATTN_SMEM_FLOATS (32*SCP + 32*KVW2 + 4*CHN*KVW2 + 1024)
#define ATTN_SMEM_BYTES (ATTN_SMEM_FLOATS * 4)

__global__ void __launch_bounds__(512) attn_kernel(
    const float* __restrict__ q, const float* __restrict__ k,
    const float* __restrict__ v, const int* __restrict__ mask,
    float* __restrict__ p_out, float* __restrict__ ctx)
{
    extern __shared__ float sm[];
    float* sc  = sm;                    // [32][1028]
    float* qs  = sc + 32*SCP;           // [32][72]
    float* kvs = qs + 32*KVW2;          // [4][64][72] ring
    float* mk  = kvs + 4*CHN*KVW2;      // [1024]

    const int b = blockIdx.z, h = blockIdx.y, i0 = blockIdx.x * 32;
    const int tid = threadIdx.x;
    const int lane = tid & 31, warp = tid >> 5;
    const int r4 = lane >> 2, c4 = lane & 3;
    const int mi_w = warp & 1;           // m16 tile
    const int njg  = warp >> 1;          // n8 group (8 groups x 8 = 64 cols)

    uint32_t kvBase = (uint32_t)__cvta_generic_to_shared(kvs);

    // chunk c: 0..15 = K, 16..31 = V; 64 keys each; buffer = c & 3
    auto issue_chunk = [&](int c) {
        const float* src = (c < 16) ? k : v;
        int j0 = (c & 15) * CHN;
        uint32_t so = (uint32_t)((c & 3) * CHN * KVW2 * 4);
        #pragma unroll
        for (int t = 0; t < 2; t++) {
            int idx = tid + t*512;
            int j = idx >> 4, d4 = (idx & 15) * 4;
            cp16(kvBase + so + (j*KVW2 + d4)*4,
                 src + ((size_t)(b*S_ + j0 + j))*E_ + h*D_ + d4);
        }
        asm volatile("cp.async.commit_group;" ::: "memory");
    };

    issue_chunk(0);
    issue_chunk(1);
    issue_chunk(2);

    {
        int i = tid >> 4, d4 = (tid & 15) * 4;
        float4 qv = *(const float4*)&q[((size_t)(b*S_ + i0 + i))*E_ + h*D_ + d4];
        qv.x *= 0.125f; qv.y *= 0.125f; qv.z *= 0.125f; qv.w *= 0.125f;
        *(float4*)&qs[i*KVW2 + d4] = qv;
    }
    for (int j = tid; j < S_; j += 512) mk[j] = (float)mask[b*S_ + j];
    __syncthreads();

    // q A-fragments for this warp's m16 tile (k-permuted: k = 2c4, 2c4+1)
    uint32_t qa[8][4];
    #pragma unroll
    for (int kk8 = 0; kk8 < 8; kk8++) {
        const float* lo = qs + (mi_w*16 + r4)*KVW2 + kk8*8 + 2*c4;
        const float* hi = qs + (mi_w*16 + r4 + 8)*KVW2 + kk8*8 + 2*c4;
        qa[kk8][0] = fbits(lo[0]);
        qa[kk8][1] = fbits(hi[0]);
        qa[kk8][2] = fbits(lo[1]);
        qa[kk8][3] = fbits(hi[1]);
    }

    // ---- phase 1: scores, 16 K chunks of 64 keys ----
    for (int c = 0; c < 16; c++) {
        asm volatile("cp.async.wait_group 2;" ::: "memory");  // chunk c ready
        __syncthreads();          // publish chunk c; everyone done with c-1
        issue_chunk(c + 3);       // overwrites buffer (c-1)&3 — safe after barrier
        const float* kc = kvs + (c & 3) * CHN * KVW2;

        float acc[4] = {0,0,0,0};
        #pragma unroll
        for (int kk8 = 0; kk8 < 8; kk8++) {
            float2 bv = *(const float2*)(kc + (njg*8 + r4)*KVW2 + kk8*8 + 2*c4);
            mma_tf32(acc, qa[kk8][0], qa[kk8][1], qa[kk8][2], qa[kk8][3],
                     fbits(bv.x), fbits(bv.y));
        }
        int n0 = c*CHN + njg*8 + 2*c4;
        int r = mi_w*16 + r4;
        *(float2*)&sc[r*SCP + n0]     = make_float2(acc[0], acc[1]);
        *(float2*)&sc[(r+8)*SCP + n0] = make_float2(acc[2], acc[3]);
    }
    __syncthreads();   // sc complete for softmax

    // ---- phase 2: softmax + streaming p write (float4); V chunks in flight ----
    for (int r = warp; r < 32; r += 16) {
        float* row = sc + r * SCP;
        float mx = -1e30f;
        for (int j = lane*4; j < 1024; j += 128) {
            float4 sv = *(float4*)&row[j];
            float4 mv = *(const float4*)&mk[j];
            sv.x = (mv.x != 0.f) ? sv.x : -1e9f;
            sv.y = (mv.y != 0.f) ? sv.y : -1e9f;
            sv.z = (mv.z != 0.f) ? sv.z : -1e9f;
            sv.w = (mv.w != 0.f) ? sv.w : -1e9f;
            *(float4*)&row[j] = sv;
            mx = fmaxf(mx, fmaxf(fmaxf(sv.x, sv.y), fmaxf(sv.z, sv.w)));
        }
        #pragma unroll
        for (int o = 16; o; o >>= 1) mx = fmaxf(mx, __shfl_xor_sync(0xffffffffu, mx, o));
        float sum = 0.f;
        for (int j = lane*4; j < 1024; j += 128) {
            float4 sv = *(float4*)&row[j];
            sv.x = __expf(sv.x - mx);
            sv.y = __expf(sv.y - mx);
            sv.z = __expf(sv.z - mx);
            sv.w = __expf(sv.w - mx);
            *(float4*)&row[j] = sv;
            sum += (sv.x + sv.y) + (sv.z + sv.w);
        }
        #pragma unroll
        for (int o = 16; o; o >>= 1) sum += __shfl_xor_sync(0xffffffffu, sum, o);
        float inv = 1.f / sum;
        float* prow = p_out + (((size_t)(b*H_ + h))*S_ + i0 + r) * S_;
        for (int j = lane*4; j < 1024; j += 128) {
            float4 sv = *(float4*)&row[j];
            float4 pv;
            pv.x = sv.x * inv; pv.y = sv.y * inv;
            pv.z = sv.z * inv; pv.w = sv.w * inv;
            __stcs((float4*)(prow + j), pv);
            pv.x = tfround(pv.x); pv.y = tfround(pv.y);
            pv.z = tfround(pv.z); pv.w = tfround(pv.w);
            *(float4*)&row[j] = pv;
        }
    }

    // ---- phase 3: out = p @ v, 16 V chunks of 64 keys ----
    float oacc[4] = {0,0,0,0};
    for (int c = 16; c < 32; c++) {
        int rem = 31 - c;
        if (rem >= 2)      asm volatile("cp.async.wait_group 2;" ::: "memory");
        else if (rem == 1) asm volatile("cp.async.wait_group 1;" ::: "memory");
        else               asm volatile("cp.async.wait_group 0;" ::: "memory");
        __syncthreads();
        if (c + 3 <= 31) issue_chunk(c + 3);
        const float* vc = kvs + (c & 3) * CHN * KVW2;
        int j0 = (c - 16) * CHN;
        #pragma unroll
        for (int kk = 0; kk < CHN; kk += 8) {
            const float* ap = sc + (mi_w*16 + r4)*SCP + j0 + kk + c4;
            uint32_t a0 = fbits(ap[0]), a1 = fbits(ap[8*SCP]);
            uint32_t a2 = fbits(ap[4]), a3 = fbits(ap[8*SCP + 4]);
            const float* bp = vc + (kk + c4)*KVW2 + njg*8 + r4;
            mma_tf32(oacc, a0, a1, a2, a3, fbits(bp[0]), fbits(bp[4*KVW2]));
        }
    }
    {
        int r = mi_w*16 + r4;
        int cc = njg*8 + 2*c4;
        size_t o0 = ((size_t)(b*S_ + i0 + r))*E_ + h*D_ + cc;
        size_t o1 = ((size_t)(b*S_ + i0 + r + 8))*E_ + h*D_ + cc;
        *(float2*)&ctx[o0] = make_float2(tfround(oacc[0]), tfround(oacc[1]));
        *(float2*)&ctx[o1] = make_float2(tfround(oacc[2]), tfround(oacc[3]));
    }
}

// ---------------------------------------------------------------------------
extern "C" void kernel_launch(void* const* d_in, const int* in_sizes, int n_in,
                              void* d_out, int out_size)
{
    const float* x    = (const float*)d_in[0];
    const int*   mask = (const int*)  d_in[1];
    const float* Wq = (const float*)d_in[2];
    const float* bq = (const float*)d_in[3];
    const float* Wk = (const float*)d_in[4];
    const float* bk = (const float*)d_in[5];
    const float* Wv = (const float*)d_in[6];
    const float* bv = (const float*)d_in[7];
    const float* Wo = (const float*)d_in[8];
    const float* bo = (const float*)d_in[9];
    const float* Wgq = (const float*)d_in[10];
    const float* bgq = (const float*)d_in[11];
    const float* Wgk = (const float*)d_in[12];
    const float* bgk = (const float*)d_in[13];
    const float* qg_wq = (const float*)d_in[14];
    const float* qg_bq = (const float*)d_in[15];
    const float* qg_wk = (const float*)d_in[16];
    const float* qg_bk = (const float*)d_in[17];
    const float* kg_wq = (const float*)d_in[18];
    const float* kg_bq = (const float*)d_in[19];
    const float* kg_wk = (const float*)d_in[20];
    const float* kg_bk = (const float*)d_in[21];

    float* out   = (float*)d_out;
    float* p_out = out + (size_t)S_ * B_ * E_;

    float *qkvb, *ctxb;
    cudaGetSymbolAddress((void**)&qkvb, g_qkv);
    cudaGetSymbolAddress((void**)&ctxb, g_ctx);
    float* qb = qkvb;
    float* kb = qkvb + (size_t)B_*S_*E_;
    float* vb = qkvb + 2*(size_t)B_*S_*E_;

    cudaFuncSetAttribute(attn_kernel, cudaFuncAttributeMaxDynamicSharedMemorySize,
                         ATTN_SMEM_BYTES);

    round_all<<<8192, 256>>>((const float4*)x, (const float4*)Wq,
                             (const float4*)Wk, (const float4*)Wv, (const float4*)Wo);
    msum_kernel<<<1, 128>>>(mask);
    mean_kernel<<<dim3(E_/64, B_), 256>>>(x, mask);

    tgemm_qkv<<<dim3(8, 32, 3), 256>>>(bq, bk, bv, qkvb);

    gproj_kernel<<<dim3(512, 2), 256>>>(Wgq, bgq, Wgk, bgk);

    gate_kernel<<<dim3(8192, 2), 256>>>(qkvb,
        qg_wq, qg_bq, qg_wk, qg_bk,
        kg_wq, kg_bq, kg_wk, kg_bk);

    attn_kernel<<<dim3(S_/32, H_, B_), 512, ATTN_SMEM_BYTES>>>(
        qb, kb, vb, mask, p_out, ctxb);

    tgemm_wo<<<dim3(8, 32), 256>>>(bo, out);
}

// round 17
// speedup vs baseline: 1.0592x; 1.0592x over previous
#include <cuda_runtime.h>
#include <cstdint>

#define B_ 4
#define S_ 1024
#define E_ 1024
#define H_ 16
#define D_ 64

__device__ float g_qkv[3*B_*S_*E_];
__device__ float g_ctx[B_*S_*E_];
__device__ float g_xtf[B_*S_*E_];
__device__ float g_wtf[4*E_*E_];
__device__ float g_g[B_*E_];
__device__ float g_gq[B_*E_];
__device__ float g_gk[B_*E_];
__device__ float g_minv[B_];

__device__ __forceinline__ uint32_t fbits(float f) { return __float_as_uint(f); }

__device__ __forceinline__ uint32_t f2tf(float f) {
    uint32_t u;
    asm("cvt.rna.tf32.f32 %0, %1;" : "=r"(u) : "f"(f));
    return u;
}
__device__ __forceinline__ float tfround(float f) {
    return __uint_as_float(f2tf(f));
}

__device__ __forceinline__ void mma_tf32(float c[4],
    uint32_t a0, uint32_t a1, uint32_t a2, uint32_t a3,
    uint32_t b0, uint32_t b1)
{
    asm volatile(
        "mma.sync.aligned.m16n8k8.row.col.f32.tf32.tf32.f32 "
        "{%0,%1,%2,%3}, {%4,%5,%6,%7}, {%8,%9}, {%0,%1,%2,%3};"
        : "+f"(c[0]), "+f"(c[1]), "+f"(c[2]), "+f"(c[3])
        : "r"(a0), "r"(a1), "r"(a2), "r"(a3), "r"(b0), "r"(b1));
}

__device__ __forceinline__ void cp16(uint32_t saddr, const void* g) {
    asm volatile("cp.async.cg.shared.global [%0], [%1], 16;" :: "r"(saddr), "l"(g));
}

// ---------------------------------------------------------------------------
__global__ void __launch_bounds__(256) round_all(
    const float4* __restrict__ x,
    const float4* __restrict__ wq, const float4* __restrict__ wk,
    const float4* __restrict__ wv, const float4* __restrict__ wo)
{
    int idx = blockIdx.x * 256 + threadIdx.x;
    const float4* src;
    float4* dst;
    if (idx < (1 << 20)) {
        src = x + idx;
        dst = (float4*)g_xtf + idx;
    } else {
        int r = idx - (1 << 20);
        int w = r >> 18, o = r & ((1 << 18) - 1);
        const float4* s = (w == 0) ? wq : (w == 1) ? wk : (w == 2) ? wv : wo;
        src = s + o;
        dst = (float4*)g_wtf + ((size_t)w << 18) + o;
    }
    float4 v = *src;
    v.x = tfround(v.x); v.y = tfround(v.y);
    v.z = tfround(v.z); v.w = tfround(v.w);
    *dst = v;
}

// ---------------------------------------------------------------------------
__global__ void msum_kernel(const int* __restrict__ mask) {
    int b = threadIdx.x >> 5, lane = threadIdx.x & 31;
    float s = 0.f;
    for (int j = lane; j < S_; j += 32) s += (float)mask[b*S_ + j];
    #pragma unroll
    for (int o = 16; o; o >>= 1) s += __shfl_xor_sync(0xffffffffu, s, o);
    if (lane == 0) g_minv[b] = 1.0f / fmaxf(s, 1e-9f);
}

__global__ void mean_kernel(const float* __restrict__ x, const int* __restrict__ mask) {
    __shared__ float part[4][64];
    int b  = blockIdx.y;
    int e0 = blockIdx.x * 64;
    int el = threadIdx.x & 63, sq = threadIdx.x >> 6;
    float acc = 0.f;
    int sbeg = sq * 256;
    for (int s = sbeg; s < sbeg + 256; s++) {
        float m = (float)mask[b*S_ + s];
        acc += x[((size_t)s*B_ + b)*E_ + e0 + el] * m;
    }
    part[sq][el] = acc;
    __syncthreads();
    if (threadIdx.x < 64) {
        float t = part[0][el] + part[1][el] + part[2][el] + part[3][el];
        g_g[b*E_ + e0 + el] = t * g_minv[b];
    }
}

// ---------------------------------------------------------------------------
// tf32 GEMM core; k-tile 32 (half the barriers of k-tile 16), 2-stage
// cp.async, LDS.64 fragment loads via k-permutation (k = kk+2c4, kk+2c4+1
// on both A and B -> identical dot product and accumulation order).
#define KT 32
#define GPAD 40
#define GSTG (128*GPAD)

__device__ __forceinline__ void tgemm_body(
    const float* __restrict__ A, const float* __restrict__ W,
    const float* __restrict__ bias, float* __restrict__ Y,
    int permIn, int permOut, int roundOut, int bx, int by,
    float (*As)[GSTG], float (*Bs)[GSTG])
{
    const int tid = threadIdx.x;
    const int lane = tid & 31, warp = tid >> 5;
    const int wm = (warp & 1) * 64, wn = (warp >> 1) * 32;
    const int r4 = lane >> 2, c4 = lane & 3;

    uint32_t aBase = (uint32_t)__cvta_generic_to_shared(&As[0][0]);
    uint32_t bBase = (uint32_t)__cvta_generic_to_shared(&Bs[0][0]);

    // loader: thread owns rows (tid>>3)+32t, col c16 (float4) for A and B
    const int lrow = tid >> 3;         // 0..31
    const int c16  = tid & 7;          // 0..7
    const float* apt[4];
    const float* wpt[4];
    uint32_t adA[4], bdB[4];
    #pragma unroll
    for (int t = 0; t < 4; t++) {
        int row = lrow + 32*t;
        int am  = by*128 + row;
        int ar  = permIn ? ((am & 1023)*B_ + (am >> 10)) : am;
        apt[t] = A + (size_t)ar*1024 + c16*4;
        wpt[t] = W + ((size_t)(bx*128 + row))*1024 + c16*4;
        adA[t] = aBase + (row*GPAD + c16*4)*4;
        bdB[t] = bBase + (row*GPAD + c16*4)*4;
    }

    auto loadStage = [&](int stg, int k0) {
        uint32_t so = (uint32_t)stg * GSTG * 4;
        #pragma unroll
        for (int t = 0; t < 4; t++) {
            cp16(adA[t] + so, apt[t] + k0);
            cp16(bdB[t] + so, wpt[t] + k0);
        }
        asm volatile("cp.async.commit_group;" ::: "memory");
    };

    float acc[4][4][4];
    #pragma unroll
    for (int mi = 0; mi < 4; mi++)
        #pragma unroll
        for (int nj = 0; nj < 4; nj++)
            #pragma unroll
            for (int t = 0; t < 4; t++) acc[mi][nj][t] = 0.f;

    loadStage(0, 0);
    for (int ks = 0; ks < 32; ks++) {
        if (ks < 31) {
            loadStage((ks + 1) & 1, (ks + 1) * KT);
            asm volatile("cp.async.wait_group 1;" ::: "memory");
        } else {
            asm volatile("cp.async.wait_group 0;" ::: "memory");
        }
        __syncthreads();
        const float* as = As[ks & 1];
        const float* bs = Bs[ks & 1];
        #pragma unroll
        for (int kk = 0; kk < KT; kk += 8) {
            uint32_t af[4][4];
            #pragma unroll
            for (int mi = 0; mi < 4; mi++) {
                float2 lo = *(const float2*)(as + (wm + mi*16 + r4)*GPAD + kk + 2*c4);
                float2 hi = *(const float2*)(as + (wm + mi*16 + r4 + 8)*GPAD + kk + 2*c4);
                af[mi][0] = fbits(lo.x);
                af[mi][1] = fbits(hi.x);
                af[mi][2] = fbits(lo.y);
                af[mi][3] = fbits(hi.y);
            }
            #pragma unroll
            for (int nj = 0; nj < 4; nj++) {
                float2 bv = *(const float2*)(bs + (wn + nj*8 + r4)*GPAD + kk + 2*c4);
                uint32_t b0 = fbits(bv.x), b1 = fbits(bv.y);
                #pragma unroll
                for (int mi = 0; mi < 4; mi++)
                    mma_tf32(acc[mi][nj], af[mi][0], af[mi][1], af[mi][2], af[mi][3], b0, b1);
            }
        }
        __syncthreads();
    }

    #pragma unroll
    for (int mi = 0; mi < 4; mi++) {
        #pragma unroll
        for (int r2 = 0; r2 < 2; r2++) {
            int m = by*128 + wm + mi*16 + r4 + r2*8;
            int orow = permOut ? ((m & 1023)*B_ + (m >> 10)) : m;
            float* yp = Y + (size_t)orow*1024 + bx*128 + wn;
            const float* bi = bias + bx*128 + wn;
            #pragma unroll
            for (int nj = 0; nj < 4; nj++) {
                int c = nj*8 + 2*c4;
                float2 val;
                val.x = acc[mi][nj][r2*2 + 0] + bi[c];
                val.y = acc[mi][nj][r2*2 + 1] + bi[c + 1];
                if (roundOut) { val.x = tfround(val.x); val.y = tfround(val.y); }
                *(float2*)(yp + c) = val;
            }
        }
    }
}

__global__ void __launch_bounds__(256) tgemm_qkv(
    const float* __restrict__ bq, const float* __restrict__ bk,
    const float* __restrict__ bv, float* __restrict__ Y)
{
    __shared__ float As[2][GSTG];
    __shared__ float Bs[2][GSTG];
    int sel = blockIdx.z;
    const float* bi = (sel == 0) ? bq : (sel == 1) ? bk : bv;
    tgemm_body(g_xtf, g_wtf + (size_t)sel*E_*E_, bi, Y + (size_t)sel*B_*S_*E_,
               1, 0, sel == 2, blockIdx.x, blockIdx.y, As, Bs);
}

__global__ void __launch_bounds__(256) tgemm_wo(
    const float* __restrict__ bias, float* __restrict__ Y)
{
    __shared__ float As[2][GSTG];
    __shared__ float Bs[2][GSTG];
    tgemm_body(g_ctx, g_wtf + (size_t)3*E_*E_, bias, Y,
               0, 1, 0, blockIdx.x, blockIdx.y, As, Bs);
}

// ---------------------------------------------------------------------------
__global__ void gproj_kernel(const float* __restrict__ Wgq, const float* __restrict__ bgq,
                             const float* __restrict__ Wgk, const float* __restrict__ bgk)
{
    const float* Wg = blockIdx.y ? Wgk : Wgq;
    const float* bg = blockIdx.y ? bgk : bgq;
    float* out      = blockIdx.y ? g_gk : g_gq;
    int gw = (blockIdx.x * blockDim.x + threadIdx.x) >> 5;
    int lane = threadIdx.x & 31;
    int b = gw >> 10, o = gw & 1023;
    float acc = 0.f;
    #pragma unroll
    for (int e = lane * 4; e < E_; e += 128) {
        float4 gv = *(const float4*)&g_g[b*E_ + e];
        float4 wv = *(const float4*)&Wg[(size_t)o*E_ + e];
        acc += gv.x*wv.x + gv.y*wv.y + gv.z*wv.z + gv.w*wv.w;
    }
    #pragma unroll
    for (int of = 16; of; of >>= 1) acc += __shfl_xor_sync(0xffffffffu, acc, of);
    if (lane == 0) out[b*E_ + o] = acc + bg[o];
}

__global__ void gate_kernel(float* __restrict__ qkv,
                            const float* __restrict__ wvq, const float* __restrict__ bvq,
                            const float* __restrict__ wgq, const float* __restrict__ bgq,
                            const float* __restrict__ wvk, const float* __restrict__ bvk,
                            const float* __restrict__ wgk, const float* __restrict__ bgk)
{
    int z = blockIdx.y;
    float* buf        = qkv + (size_t)z * B_*S_*E_;
    const float* gbuf = z ? g_gk : g_gq;
    const float* wv   = z ? wvk : wvq;
    const float* bvp  = z ? bvk : bvq;
    const float* wg   = z ? wgk : wgq;
    const float* bgp  = z ? bgk : bgq;

    int gw   = (blockIdx.x * blockDim.x + threadIdx.x) >> 5;
    int lane = threadIdx.x & 31;
    int b = gw >> 14, h = (gw >> 10) & 15, s = gw & 1023;
    size_t off = ((size_t)(b*S_ + s))*E_ + h*D_;
    int goff = b*E_ + h*D_;
    float q0 = buf[off + lane],        q1 = buf[off + 32 + lane];
    float g0 = gbuf[goff + lane],      g1 = gbuf[goff + 32 + lane];
    float part = q0*wv[lane] + q1*wv[32 + lane] + g0*wg[lane] + g1*wg[32 + lane];
    #pragma unroll
    for (int o = 16; o; o >>= 1) part += __shfl_xor_sync(0xffffffffu, part, o);
    float alpha = 1.f / (1.f + __expf(-(part + bvp[0] + bgp[0])));
    buf[off + lane]      = tfround(q0 + alpha * (g0 - q0));
    buf[off + 32 + lane] = tfround(q1 + alpha * (g1 - q1));
}

// ---------------------------------------------------------------------------
// fused attention (R15 proven): 32 q-rows/CTA, 512 threads, 128-key
// double-buffered chunks; phase-1 warp = n8 group computing both m16 tiles.
// Phase 2 float4-vectorized.
#define SCP 1028
#define KVW2 72
#define CH 128
#define ATTN_SMEM_FLOATS (32*SCP + 32*KVW2 + 2*CH*KVW2 + 1024)
#define ATTN_SMEM_BYTES (ATTN_SMEM_FLOATS * 4)

__global__ void __launch_bounds__(512) attn_kernel(
    const float* __restrict__ q, const float* __restrict__ k,
    const float* __restrict__ v, const int* __restrict__ mask,
    float* __restrict__ p_out, float* __restrict__ ctx)
{
    extern __shared__ float sm[];
    float* sc  = sm;                    // [32][1028]
    float* qs  = sc + 32*SCP;           // [32][72]
    float* kvs = qs + 32*KVW2;          // [2][128][72]
    float* mk  = kvs + 2*CH*KVW2;       // [1024]

    const int b = blockIdx.z, h = blockIdx.y, i0 = blockIdx.x * 32;
    const int tid = threadIdx.x;
    const int lane = tid & 31, warp = tid >> 5;
    const int r4 = lane >> 2, c4 = lane & 3;
    const int mi_w = warp & 1;
    const int njg  = warp >> 1;

    uint32_t kvBase = (uint32_t)__cvta_generic_to_shared(kvs);

    auto issue_chunk = [&](int c) {
        const float* src = (c < 8) ? k : v;
        int j0 = (c & 7) * CH;
        uint32_t so = (uint32_t)((c & 1) * CH * KVW2 * 4);
        #pragma unroll
        for (int t = 0; t < 4; t++) {
            int idx = tid + t*512;
            int j = idx >> 4, d4 = (idx & 15) * 4;
            cp16(kvBase + so + (j*KVW2 + d4)*4,
                 src + ((size_t)(b*S_ + j0 + j))*E_ + h*D_ + d4);
        }
        asm volatile("cp.async.commit_group;" ::: "memory");
    };

    issue_chunk(0);

    {
        int i = tid >> 4, d4 = (tid & 15) * 4;
        float4 qv = *(const float4*)&q[((size_t)(b*S_ + i0 + i))*E_ + h*D_ + d4];
        qv.x *= 0.125f; qv.y *= 0.125f; qv.z *= 0.125f; qv.w *= 0.125f;
        *(float4*)&qs[i*KVW2 + d4] = qv;
    }
    for (int j = tid; j < S_; j += 512) mk[j] = (float)mask[b*S_ + j];
    __syncthreads();

    uint32_t qa[2][8][4];
    #pragma unroll
    for (int mi = 0; mi < 2; mi++) {
        #pragma unroll
        for (int kk8 = 0; kk8 < 8; kk8++) {
            const float* lo = qs + (mi*16 + r4)*KVW2 + kk8*8 + 2*c4;
            const float* hi = qs + (mi*16 + r4 + 8)*KVW2 + kk8*8 + 2*c4;
            qa[mi][kk8][0] = fbits(lo[0]);
            qa[mi][kk8][1] = fbits(hi[0]);
            qa[mi][kk8][2] = fbits(lo[1]);
            qa[mi][kk8][3] = fbits(hi[1]);
        }
    }

    // ---- phase 1: scores; warp = n8 group over full 128-col chunk ----
    for (int jt = 0; jt < 8; jt++) {
        issue_chunk(jt + 1);
        asm volatile("cp.async.wait_group 1;" ::: "memory");
        __syncthreads();
        const float* kc = kvs + (jt & 1) * CH * KVW2;

        float acc[2][4] = {{0,0,0,0},{0,0,0,0}};
        #pragma unroll
        for (int kk8 = 0; kk8 < 8; kk8++) {
            float2 bv = *(const float2*)(kc + (warp*8 + r4)*KVW2 + kk8*8 + 2*c4);
            uint32_t b0 = fbits(bv.x), b1 = fbits(bv.y);
            mma_tf32(acc[0], qa[0][kk8][0], qa[0][kk8][1], qa[0][kk8][2], qa[0][kk8][3], b0, b1);
            mma_tf32(acc[1], qa[1][kk8][0], qa[1][kk8][1], qa[1][kk8][2], qa[1][kk8][3], b0, b1);
        }
        int n0 = jt*CH + warp*8 + 2*c4;
        #pragma unroll
        for (int mi = 0; mi < 2; mi++) {
            int r = mi*16 + r4;
            *(float2*)&sc[r*SCP + n0]     = make_float2(acc[mi][0], acc[mi][1]);
            *(float2*)&sc[(r+8)*SCP + n0] = make_float2(acc[mi][2], acc[mi][3]);
        }
        __syncthreads();
    }

    // ---- phase 2: softmax + streaming p write, float4 vectorized ----
    for (int r = warp; r < 32; r += 16) {
        float* row = sc + r * SCP;
        float mx = -1e30f;
        for (int j = lane*4; j < 1024; j += 128) {
            float4 sv = *(float4*)&row[j];
            float4 mv = *(const float4*)&mk[j];
            sv.x = (mv.x != 0.f) ? sv.x : -1e9f;
            sv.y = (mv.y != 0.f) ? sv.y : -1e9f;
            sv.z = (mv.z != 0.f) ? sv.z : -1e9f;
            sv.w = (mv.w != 0.f) ? sv.w : -1e9f;
            *(float4*)&row[j] = sv;
            mx = fmaxf(mx, fmaxf(fmaxf(sv.x, sv.y), fmaxf(sv.z, sv.w)));
        }
        #pragma unroll
        for (int o = 16; o; o >>= 1) mx = fmaxf(mx, __shfl_xor_sync(0xffffffffu, mx, o));
        float sum = 0.f;
        for (int j = lane*4; j < 1024; j += 128) {
            float4 sv = *(float4*)&row[j];
            sv.x = __expf(sv.x - mx);
            sv.y = __expf(sv.y - mx);
            sv.z = __expf(sv.z - mx);
            sv.w = __expf(sv.w - mx);
            *(float4*)&row[j] = sv;
            sum += (sv.x + sv.y) + (sv.z + sv.w);
        }
        #pragma unroll
        for (int o = 16; o; o >>= 1) sum += __shfl_xor_sync(0xffffffffu, sum, o);
        float inv = 1.f / sum;
        float* prow = p_out + (((size_t)(b*H_ + h))*S_ + i0 + r) * S_;
        for (int j = lane*4; j < 1024; j += 128) {
            float4 sv = *(float4*)&row[j];
            float4 pv;
            pv.x = sv.x * inv; pv.y = sv.y * inv;
            pv.z = sv.z * inv; pv.w = sv.w * inv;
            __stcs((float4*)(prow + j), pv);
            pv.x = tfround(pv.x); pv.y = tfround(pv.y);
            pv.z = tfround(pv.z); pv.w = tfround(pv.w);
            *(float4*)&row[j] = pv;
        }
    }

    // ---- phase 3: out = p @ v ----
    float oacc[4] = {0,0,0,0};
    for (int c = 8; c < 16; c++) {
        if (c < 15) {
            issue_chunk(c + 1);
            asm volatile("cp.async.wait_group 1;" ::: "memory");
        } else {
            asm volatile("cp.async.wait_group 0;" ::: "memory");
        }
        __syncthreads();
        const float* vc = kvs + (c & 1) * CH * KVW2;
        int j0 = (c - 8) * CH;
        #pragma unroll
        for (int kk = 0; kk < CH; kk += 8) {
            const float* ap = sc + (mi_w*16 + r4)*SCP + j0 + kk + c4;
            uint32_t a0 = fbits(ap[0]), a1 = fbits(ap[8*SCP]);
            uint32_t a2 = fbits(ap[4]), a3 = fbits(ap[8*SCP + 4]);
            const float* bp = vc + (kk + c4)*KVW2 + njg*8 + r4;
            mma_tf32(oacc, a0, a1, a2, a3, fbits(bp[0]), fbits(bp[4*KVW2]));
        }
        __syncthreads();
    }
    {
        int r = mi_w*16 + r4;
        int cc = njg*8 + 2*c4;
        size_t o0 = ((size_t)(b*S_ + i0 + r))*E_ + h*D_ + cc;
        size_t o1 = ((size_t)(b*S_ + i0 + r + 8))*E_ + h*D_ + cc;
        *(float2*)&ctx[o0] = make_float2(tfround(oacc[0]), tfround(oacc[1]));
        *(float2*)&ctx[o1] = make_float2(tfround(oacc[2]), tfround(oacc[3]));
    }
}

// ---------------------------------------------------------------------------
extern "C" void kernel_launch(void* const* d_in, const int* in_sizes, int n_in,
                              void* d_out, int out_size)
{
    const float* x    = (const float*)d_in[0];
    const int*   mask = (const int*)  d_in[1];
    const float* Wq = (const float*)d_in[2];
    const float* bq = (const float*)d_in[3];
    const float* Wk = (const float*)d_in[4];
    const float* bk = (const float*)d_in[5];
    const float* Wv = (const float*)d_in[6];
    const float* bv = (const float*)d_in[7];
    const float* Wo = (const float*)d_in[8];
    const float* bo = (const float*)d_in[9];
    const float* Wgq = (const float*)d_in[10];
    const float* bgq = (const float*)d_in[11];
    const float* Wgk = (const float*)d_in[12];
    const float* bgk = (const float*)d_in[13];
    const float* qg_wq = (const float*)d_in[14];
    const float* qg_bq = (const float*)d_in[15];
    const float* qg_wk = (const float*)d_in[16];
    const float* qg_bk = (const float*)d_in[17];
    const float* kg_wq = (const float*)d_in[18];
    const float* kg_bq = (const float*)d_in[19];
    const float* kg_wk = (const float*)d_in[20];
    const float* kg_bk = (const float*)d_in[21];

    float* out   = (float*)d_out;
    float* p_out = out + (size_t)S_ * B_ * E_;

    float *qkvb, *ctxb;
    cudaGetSymbolAddress((void**)&qkvb, g_qkv);
    cudaGetSymbolAddress((void**)&ctxb, g_ctx);
    float* qb = qkvb;
    float* kb = qkvb + (size_t)B_*S_*E_;
    float* vb = qkvb + 2*(size_t)B_*S_*E_;

    cudaFuncSetAttribute(attn_kernel, cudaFuncAttributeMaxDynamicSharedMemorySize,
                         ATTN_SMEM_BYTES);

    round_all<<<8192, 256>>>((const float4*)x, (const float4*)Wq,
                             (const float4*)Wk, (const float4*)Wv, (const float4*)Wo);
    msum_kernel<<<1, 128>>>(mask);
    mean_kernel<<<dim3(E_/64, B_), 256>>>(x, mask);

    tgemm_qkv<<<dim3(8, 32, 3), 256>>>(bq, bk, bv, qkvb);

    gproj_kernel<<<dim3(512, 2), 256>>>(Wgq, bgq, Wgk, bgk);

    gate_kernel<<<dim3(8192, 2), 256>>>(qkvb,
        qg_wq, qg_bq, qg_wk, qg_bk,
        kg_wq, kg_bq, kg_wk, kg_bk);

    attn_kernel<<<dim3(S_/32, H_, B_), 512, ATTN_SMEM_BYTES>>>(
        qb, kb, vb, mask, p_out, ctxb);

    tgemm_wo<<<dim3(8, 32), 256>>>(bo, out);
}